// round 1
// baseline (speedup 1.0000x reference)
#include <cuda_runtime.h>

#define D    512
#define KCB  2048
#define NQ   8
#define BT   16384            // B*T = 8*2048
#define NT   16               // number of 128-wide N tiles (2048/128)
#define QOFF (BT * D)         // 8388608: start of indices in out
#define LOFF (QOFF + BT * NQ) // 8519680: loss scalar

// ---- scratch (static device globals; no allocations) ----
__device__ float g_residual[BT * D];      // 32 MB
__device__ float g_rownorm[BT];           // ||r||^2 per row
__device__ float g_cnorm[KCB];            // ||cb_k||^2 per code (current level)
__device__ float g_pval[BT * NT];         // partial argmin values
__device__ int   g_pidx[BT * NT];         // partial argmin indices
__device__ float g_losspart[NQ * (BT / 8)]; // per-block loss partials (deterministic)

// ---------------------------------------------------------------------------
// init: residual = x, quantized(out) = 0
// ---------------------------------------------------------------------------
__global__ void init_kernel(const float* __restrict__ x, float* __restrict__ out) {
    int i = blockIdx.x * blockDim.x + threadIdx.x;
    g_residual[i] = x[i];
    out[i] = 0.0f;
}

// one warp per row: rownorm = sum(r*r)
__global__ void rownorm_kernel() {
    int row  = blockIdx.x * 8 + (threadIdx.x >> 5);
    int lane = threadIdx.x & 31;
    const float* r = g_residual + row * D;
    float s = 0.0f;
#pragma unroll
    for (int d = lane; d < D; d += 32) { float v = r[d]; s += v * v; }
#pragma unroll
    for (int o = 16; o; o >>= 1) s += __shfl_xor_sync(0xffffffffu, s, o);
    if (lane == 0) g_rownorm[row] = s;
}

// one warp per code: cnorm = sum(cb*cb)
__global__ void cbnorm_kernel(const float* __restrict__ cb) {
    int code = blockIdx.x * 8 + (threadIdx.x >> 5);
    int lane = threadIdx.x & 31;
    const float* c = cb + code * D;
    float s = 0.0f;
#pragma unroll
    for (int d = lane; d < D; d += 32) { float v = c[d]; s += v * v; }
#pragma unroll
    for (int o = 16; o; o >>= 1) s += __shfl_xor_sync(0xffffffffu, s, o);
    if (lane == 0) g_cnorm[code] = s;
}

// ---------------------------------------------------------------------------
// Fused fp32 SGEMM (scores = residual @ cb^T) + partial argmin per 128-col tile.
// CTA tile: 128(M) x 128(N), K-chunk 8, double-buffered smem, 8x8 microtiles.
// d_k = (A - 2*e_k) + c_k   (replicates reference formula & rounding order)
// argmin with strict-<, ascending k  => first-minimum semantics.
// ---------------------------------------------------------------------------
__global__ __launch_bounds__(256, 2) void gemm_argmin_kernel(const float* __restrict__ cb) {
    __shared__ float As[2][8][128];
    __shared__ float Bs[2][8][128];
    __shared__ float sval[128][16];
    __shared__ int   sidx[128][16];

    const int tid   = threadIdx.x;
    const int mBase = blockIdx.x * 128;
    const int nBase = blockIdx.y * 128;
    const int tx = tid & 15;
    const int ty = tid >> 4;

    float acc[8][8];
#pragma unroll
    for (int i = 0; i < 8; i++)
#pragma unroll
        for (int j = 0; j < 8; j++) acc[i][j] = 0.0f;

    const int lrow = tid >> 1;
    const int lcol = (tid & 1) << 2;
    const float* Ag = g_residual + (size_t)(mBase + lrow) * D + lcol;
    const float* Bg = cb        + (size_t)(nBase + lrow) * D + lcol;

    // prologue: stage 0
    {
        float4 a = *(const float4*)Ag;
        float4 b = *(const float4*)Bg;
        As[0][lcol + 0][lrow] = a.x; As[0][lcol + 1][lrow] = a.y;
        As[0][lcol + 2][lrow] = a.z; As[0][lcol + 3][lrow] = a.w;
        Bs[0][lcol + 0][lrow] = b.x; Bs[0][lcol + 1][lrow] = b.y;
        Bs[0][lcol + 2][lrow] = b.z; Bs[0][lcol + 3][lrow] = b.w;
    }
    __syncthreads();

    for (int kt = 1; kt <= 64; ++kt) {
        const int cur = (kt - 1) & 1;
        const int nxt = kt & 1;
        float4 a2, b2;
        if (kt < 64) {
            a2 = *(const float4*)(Ag + kt * 8);
            b2 = *(const float4*)(Bg + kt * 8);
        }
#pragma unroll
        for (int kk = 0; kk < 8; ++kk) {
            float ar[8], br[8];
            *(float4*)&ar[0] = *(const float4*)&As[cur][kk][ty * 8];
            *(float4*)&ar[4] = *(const float4*)&As[cur][kk][ty * 8 + 4];
            *(float4*)&br[0] = *(const float4*)&Bs[cur][kk][tx * 8];
            *(float4*)&br[4] = *(const float4*)&Bs[cur][kk][tx * 8 + 4];
#pragma unroll
            for (int i = 0; i < 8; i++)
#pragma unroll
                for (int j = 0; j < 8; j++)
                    acc[i][j] += ar[i] * br[j];
        }
        if (kt < 64) {
            As[nxt][lcol + 0][lrow] = a2.x; As[nxt][lcol + 1][lrow] = a2.y;
            As[nxt][lcol + 2][lrow] = a2.z; As[nxt][lcol + 3][lrow] = a2.w;
            Bs[nxt][lcol + 0][lrow] = b2.x; Bs[nxt][lcol + 1][lrow] = b2.y;
            Bs[nxt][lcol + 2][lrow] = b2.z; Bs[nxt][lcol + 3][lrow] = b2.w;
        }
        __syncthreads();
    }

    // epilogue: per-thread argmin over its 8 cols (ascending j, strict <)
    float An[8], cn[8];
#pragma unroll
    for (int i = 0; i < 8; i++) An[i] = g_rownorm[mBase + ty * 8 + i];
#pragma unroll
    for (int j = 0; j < 8; j++) cn[j] = g_cnorm[nBase + tx * 8 + j];

#pragma unroll
    for (int i = 0; i < 8; i++) {
        float bv = 3.0e38f;
        int   bj = 0;
#pragma unroll
        for (int j = 0; j < 8; j++) {
            float dv = (An[i] - 2.0f * acc[i][j]) + cn[j];
            if (dv < bv) { bv = dv; bj = j; }
        }
        sval[ty * 8 + i][tx] = bv;
        sidx[ty * 8 + i][tx] = nBase + tx * 8 + bj;
    }
    __syncthreads();

    // 16 -> 1 reduce per row (ascending tx, strict <), 128 threads
    if (tid < 128) {
        float bv = sval[tid][0];
        int   bi = sidx[tid][0];
#pragma unroll
        for (int t = 1; t < 16; t++) {
            float v = sval[tid][t];
            if (v < bv) { bv = v; bi = sidx[tid][t]; }
        }
        int row = mBase + tid;
        g_pval[row * NT + blockIdx.y] = bv;
        g_pidx[row * NT + blockIdx.y] = bi;
    }
}

// ---------------------------------------------------------------------------
// update: final argmin across N-tiles, gather code, quantized += q,
// residual -= q, rownorm(next) = loss partial = sum((r-q)^2)
// ---------------------------------------------------------------------------
__global__ void update_kernel(const float* __restrict__ cb, float* __restrict__ out, int level) {
    __shared__ float bsum[8];
    const int wid  = threadIdx.x >> 5;
    const int row  = blockIdx.x * 8 + wid;
    const int lane = threadIdx.x & 31;

    int idx = 0;
    if (lane == 0) {
        float bv = g_pval[row * NT];
        int   bi = g_pidx[row * NT];
#pragma unroll
        for (int t = 1; t < NT; t++) {
            float v = g_pval[row * NT + t];
            if (v < bv) { bv = v; bi = g_pidx[row * NT + t]; }
        }
        idx = bi;
        out[QOFF + row * NQ + level] = (float)bi;   // indices as f32 values
    }
    idx = __shfl_sync(0xffffffffu, idx, 0);

    const float* c = cb + (size_t)idx * D;
    float* r = g_residual + (size_t)row * D;
    float* q = out + (size_t)row * D;

    float s = 0.0f;
#pragma unroll
    for (int d = lane; d < D; d += 32) {
        float cv = c[d];
        float rv = r[d];
        q[d] += cv;               // quantized accumulates in level order
        float nr = rv - cv;       // new residual (= r_before - q_lvl)
        r[d] = nr;
        s += nr * nr;             // commit/codebook loss term & next rownorm
    }
#pragma unroll
    for (int o = 16; o; o >>= 1) s += __shfl_xor_sync(0xffffffffu, s, o);
    if (lane == 0) { g_rownorm[row] = s; bsum[wid] = s; }
    __syncthreads();
    if (threadIdx.x == 0) {
        float t = 0.0f;
#pragma unroll
        for (int w = 0; w < 8; w++) t += bsum[w];
        g_losspart[level * (BT / 8) + blockIdx.x] = t;
    }
}

// straight-through estimator rounding: out = x + (quantized - x)  (matches ref)
__global__ void ste_kernel(const float* __restrict__ x, float* __restrict__ out) {
    int i = blockIdx.x * blockDim.x + threadIdx.x;
    float xv = x[i];
    out[i] = xv + (out[i] - xv);
}

// deterministic loss reduce:  loss = 1.25 * sum / (B*T*D) / NQ
__global__ void finalize_kernel(float* __restrict__ out) {
    __shared__ float sb[256];
    float s = 0.0f;
    for (int i = threadIdx.x; i < NQ * (BT / 8); i += 256) s += g_losspart[i];
    sb[threadIdx.x] = s;
    __syncthreads();
    for (int o = 128; o; o >>= 1) {
        if (threadIdx.x < o) sb[threadIdx.x] += sb[threadIdx.x + o];
        __syncthreads();
    }
    if (threadIdx.x == 0)
        out[LOFF] = sb[0] * (0.25f + 1.0f) / (8388608.0f * (float)NQ);
}

// ---------------------------------------------------------------------------
extern "C" void kernel_launch(void* const* d_in, const int* in_sizes, int n_in,
                              void* d_out, int out_size) {
    const float* x   = (const float*)d_in[0];
    const float* cbs = (const float*)d_in[1];
    float* out = (float*)d_out;

    init_kernel<<<(BT * D) / 256, 256>>>(x, out);
    rownorm_kernel<<<BT / 8, 256>>>();

    for (int q = 0; q < NQ; ++q) {
        const float* cb = cbs + (size_t)q * KCB * D;
        cbnorm_kernel<<<KCB / 8, 256>>>(cb);
        dim3 grid(BT / 128, KCB / 128);
        gemm_argmin_kernel<<<grid, 256>>>(cb);
        update_kernel<<<BT / 8, 256>>>(cb, out, q);
    }

    ste_kernel<<<(BT * D) / 256, 256>>>(x, out);
    finalize_kernel<<<1, 256>>>(out);
}

// round 3
// speedup vs baseline: 2.0747x; 2.0747x over previous
#include <cuda_runtime.h>

#define D    512
#define KCB  2048
#define NQ   8
#define BT   16384            // B*T = 8*2048
#define NT   16               // number of 128-wide N tiles (2048/128)
#define QOFF (BT * D)         // 8388608: start of indices in out
#define LOFF (QOFF + BT * NQ) // 8519680: loss scalar

typedef unsigned long long u64;

// ---- scratch (static device globals; no allocations) ----
static __device__ float g_residual[BT * D];      // 32 MB
static __device__ float g_rownorm[BT];           // ||r||^2 per row
static __device__ float g_cnorm[KCB];            // ||cb_k||^2 per code (current level)
static __device__ float g_pval[BT * NT];         // partial argmin values
static __device__ int   g_pidx[BT * NT];         // partial argmin indices
static __device__ float g_losspart[NQ * (BT / 8)]; // per-block loss partials

// ---------------------------------------------------------------------------
// init: residual = x, quantized(out) = 0
// ---------------------------------------------------------------------------
__global__ void init_kernel(const float* __restrict__ x, float* __restrict__ out) {
    int i = blockIdx.x * blockDim.x + threadIdx.x;
    g_residual[i] = x[i];
    out[i] = 0.0f;
}

// one warp per row: rownorm = sum(r*r)
__global__ void rownorm_kernel() {
    int row  = blockIdx.x * 8 + (threadIdx.x >> 5);
    int lane = threadIdx.x & 31;
    const float* r = g_residual + row * D;
    float s = 0.0f;
#pragma unroll
    for (int d = lane; d < D; d += 32) { float v = r[d]; s += v * v; }
#pragma unroll
    for (int o = 16; o; o >>= 1) s += __shfl_xor_sync(0xffffffffu, s, o);
    if (lane == 0) g_rownorm[row] = s;
}

// one warp per code: cnorm = sum(cb*cb)
__global__ void cbnorm_kernel(const float* __restrict__ cb) {
    int code = blockIdx.x * 8 + (threadIdx.x >> 5);
    int lane = threadIdx.x & 31;
    const float* c = cb + code * D;
    float s = 0.0f;
#pragma unroll
    for (int d = lane; d < D; d += 32) { float v = c[d]; s += v * v; }
#pragma unroll
    for (int o = 16; o; o >>= 1) s += __shfl_xor_sync(0xffffffffu, s, o);
    if (lane == 0) g_cnorm[code] = s;
}

// ---------------------------------------------------------------------------
// Fused fp32 SGEMM via packed fma.rn.f32x2 (FFMA2) + partial argmin.
// CTA tile: 256(M) x 128(N), per-thread 16x8, K-chunk 8, double-buffered smem.
// Accumulators pack two M-rows per 64-bit register; B operand duplicated via
// mov.b64 {b,b}. Per-lane arithmetic is bit-identical IEEE fp32 FMA in the
// same (kt, kk) order as the reference-matching R1 kernel.
// d_k = (A - 2*e_k) + c_k ; argmin strict-<, ascending k.
// ---------------------------------------------------------------------------
__global__ __launch_bounds__(256, 1) void gemm_argmin_kernel(const float* __restrict__ cb) {
    __shared__ union {
        struct { float As[2][8][256]; float Bs[2][8][128]; } g; // 24 KB
        struct { float sval[256][16]; int sidx[256][16]; } e;   // 32 KB
    } sm;

    const int tid   = threadIdx.x;
    const int mBase = blockIdx.x * 256;
    const int nBase = blockIdx.y * 128;
    const int tx = tid & 15;        // N subtile  (cols tx*8 .. +8)
    const int ty = tid >> 4;        // M subtile  (rows ty*16 .. +16)

    u64 acc[8][8];                  // [i-pair][j] : rows (2p, 2p+1), col j
#pragma unroll
    for (int p = 0; p < 8; p++)
#pragma unroll
        for (int j = 0; j < 8; j++) acc[p][j] = 0ull;

    // staging: thread loads A rows lrow & lrow+128 (float4 each), B row lrow.
    const int lrow = tid >> 1;
    const int lcol = (tid & 1) << 2;
    const float* AgA = g_residual + (size_t)(mBase + lrow) * D + lcol;
    const float* AgB = g_residual + (size_t)(mBase + lrow + 128) * D + lcol;
    const float* Bg  = cb        + (size_t)(nBase + lrow) * D + lcol;

    // prologue: stage 0
    {
        float4 a1 = *(const float4*)AgA;
        float4 a2 = *(const float4*)AgB;
        float4 b  = *(const float4*)Bg;
        sm.g.As[0][lcol + 0][lrow] = a1.x; sm.g.As[0][lcol + 1][lrow] = a1.y;
        sm.g.As[0][lcol + 2][lrow] = a1.z; sm.g.As[0][lcol + 3][lrow] = a1.w;
        sm.g.As[0][lcol + 0][lrow + 128] = a2.x; sm.g.As[0][lcol + 1][lrow + 128] = a2.y;
        sm.g.As[0][lcol + 2][lrow + 128] = a2.z; sm.g.As[0][lcol + 3][lrow + 128] = a2.w;
        sm.g.Bs[0][lcol + 0][lrow] = b.x; sm.g.Bs[0][lcol + 1][lrow] = b.y;
        sm.g.Bs[0][lcol + 2][lrow] = b.z; sm.g.Bs[0][lcol + 3][lrow] = b.w;
    }
    __syncthreads();

    for (int kt = 1; kt <= 64; ++kt) {
        const int cur = (kt - 1) & 1;
        const int nxt = kt & 1;
        float4 a1, a2, b2;
        if (kt < 64) {
            a1 = *(const float4*)(AgA + kt * 8);
            a2 = *(const float4*)(AgB + kt * 8);
            b2 = *(const float4*)(Bg  + kt * 8);
        }
#pragma unroll
        for (int kk = 0; kk < 8; ++kk) {
            // A: 16 consecutive rows -> 8 natural 64-bit pairs (4x LDS.128)
            u64 a8[8];
            const u64* ap = (const u64*)&sm.g.As[cur][kk][ty * 16];
#pragma unroll
            for (int p = 0; p < 8; p++) a8[p] = ap[p];
            // B: 8 floats (2x LDS.128), duplicate into pairs on ALU pipe
            float bv[8];
            *(float4*)&bv[0] = *(const float4*)&sm.g.Bs[cur][kk][tx * 8];
            *(float4*)&bv[4] = *(const float4*)&sm.g.Bs[cur][kk][tx * 8 + 4];
            u64 bd[8];
#pragma unroll
            for (int j = 0; j < 8; j++)
                asm("mov.b64 %0, {%1, %1};" : "=l"(bd[j]) : "f"(bv[j]));
#pragma unroll
            for (int p = 0; p < 8; p++)
#pragma unroll
                for (int j = 0; j < 8; j++)
                    asm("fma.rn.f32x2 %0, %1, %2, %0;"
                        : "+l"(acc[p][j]) : "l"(a8[p]), "l"(bd[j]));
        }
        if (kt < 64) {
            sm.g.As[nxt][lcol + 0][lrow] = a1.x; sm.g.As[nxt][lcol + 1][lrow] = a1.y;
            sm.g.As[nxt][lcol + 2][lrow] = a1.z; sm.g.As[nxt][lcol + 3][lrow] = a1.w;
            sm.g.As[nxt][lcol + 0][lrow + 128] = a2.x; sm.g.As[nxt][lcol + 1][lrow + 128] = a2.y;
            sm.g.As[nxt][lcol + 2][lrow + 128] = a2.z; sm.g.As[nxt][lcol + 3][lrow + 128] = a2.w;
            sm.g.Bs[nxt][lcol + 0][lrow] = b2.x; sm.g.Bs[nxt][lcol + 1][lrow] = b2.y;
            sm.g.Bs[nxt][lcol + 2][lrow] = b2.z; sm.g.Bs[nxt][lcol + 3][lrow] = b2.w;
        }
        __syncthreads();
    }
    // (last __syncthreads guarantees all smem GEMM reads done before union reuse)

    // epilogue: per-thread argmin over its 8 cols, 16 rows (ascending j, strict <)
    float An[16], cn[8];
#pragma unroll
    for (int i = 0; i < 16; i++) An[i] = g_rownorm[mBase + ty * 16 + i];
#pragma unroll
    for (int j = 0; j < 8; j++) cn[j] = g_cnorm[nBase + tx * 8 + j];

#pragma unroll
    for (int i = 0; i < 16; i++) {
        float bvv = 3.0e38f;
        int   bj = 0;
#pragma unroll
        for (int j = 0; j < 8; j++) {
            float lo, hi;
            asm("mov.b64 {%0, %1}, %2;" : "=f"(lo), "=f"(hi) : "l"(acc[i >> 1][j]));
            float e = (i & 1) ? hi : lo;
            float dv = (An[i] - 2.0f * e) + cn[j];
            if (dv < bvv) { bvv = dv; bj = j; }
        }
        sm.e.sval[ty * 16 + i][tx] = bvv;
        sm.e.sidx[ty * 16 + i][tx] = nBase + tx * 8 + bj;
    }
    __syncthreads();

    // 16 -> 1 reduce per row (ascending tx, strict <), 256 threads = 256 rows
    {
        float bvv = sm.e.sval[tid][0];
        int   bi  = sm.e.sidx[tid][0];
#pragma unroll
        for (int t = 1; t < 16; t++) {
            float v = sm.e.sval[tid][t];
            if (v < bvv) { bvv = v; bi = sm.e.sidx[tid][t]; }
        }
        int row = mBase + tid;
        g_pval[row * NT + blockIdx.y] = bvv;
        g_pidx[row * NT + blockIdx.y] = bi;
    }
}

// ---------------------------------------------------------------------------
// update: final argmin across N-tiles, gather code, quantized += q,
// residual -= q, rownorm(next) = loss partial = sum((r-q)^2)
// ---------------------------------------------------------------------------
__global__ void update_kernel(const float* __restrict__ cb, float* __restrict__ out, int level) {
    __shared__ float bsum[8];
    const int wid  = threadIdx.x >> 5;
    const int row  = blockIdx.x * 8 + wid;
    const int lane = threadIdx.x & 31;

    int idx = 0;
    if (lane == 0) {
        float bv = g_pval[row * NT];
        int   bi = g_pidx[row * NT];
#pragma unroll
        for (int t = 1; t < NT; t++) {
            float v = g_pval[row * NT + t];
            if (v < bv) { bv = v; bi = g_pidx[row * NT + t]; }
        }
        idx = bi;
        out[QOFF + row * NQ + level] = (float)bi;   // indices as f32 values
    }
    idx = __shfl_sync(0xffffffffu, idx, 0);

    const float* c = cb + (size_t)idx * D;
    float* r = g_residual + (size_t)row * D;
    float* q = out + (size_t)row * D;

    float s = 0.0f;
#pragma unroll
    for (int d = lane; d < D; d += 32) {
        float cv = c[d];
        float rv = r[d];
        q[d] += cv;               // quantized accumulates in level order
        float nr = rv - cv;       // new residual (= r_before - q_lvl)
        r[d] = nr;
        s += nr * nr;             // commit/codebook loss term & next rownorm
    }
#pragma unroll
    for (int o = 16; o; o >>= 1) s += __shfl_xor_sync(0xffffffffu, s, o);
    if (lane == 0) { g_rownorm[row] = s; bsum[wid] = s; }
    __syncthreads();
    if (threadIdx.x == 0) {
        float t = 0.0f;
#pragma unroll
        for (int w = 0; w < 8; w++) t += bsum[w];
        g_losspart[level * (BT / 8) + blockIdx.x] = t;
    }
}

// straight-through estimator rounding: out = x + (quantized - x)  (matches ref)
__global__ void ste_kernel(const float* __restrict__ x, float* __restrict__ out) {
    int i = blockIdx.x * blockDim.x + threadIdx.x;
    float xv = x[i];
    out[i] = xv + (out[i] - xv);
}

// deterministic loss reduce:  loss = 1.25 * sum / (B*T*D) / NQ
__global__ void finalize_kernel(float* __restrict__ out) {
    __shared__ float sb[256];
    float s = 0.0f;
    for (int i = threadIdx.x; i < NQ * (BT / 8); i += 256) s += g_losspart[i];
    sb[threadIdx.x] = s;
    __syncthreads();
    for (int o = 128; o; o >>= 1) {
        if (threadIdx.x < o) sb[threadIdx.x] += sb[threadIdx.x + o];
        __syncthreads();
    }
    if (threadIdx.x == 0)
        out[LOFF] = sb[0] * (0.25f + 1.0f) / (8388608.0f * (float)NQ);
}

// ---------------------------------------------------------------------------
extern "C" void kernel_launch(void* const* d_in, const int* in_sizes, int n_in,
                              void* d_out, int out_size) {
    const float* x   = (const float*)d_in[0];
    const float* cbs = (const float*)d_in[1];
    float* out = (float*)d_out;

    init_kernel<<<(BT * D) / 256, 256>>>(x, out);
    rownorm_kernel<<<BT / 8, 256>>>();

    for (int q = 0; q < NQ; ++q) {
        const float* cb = cbs + (size_t)q * KCB * D;
        cbnorm_kernel<<<KCB / 8, 256>>>(cb);
        dim3 grid(BT / 256, KCB / 128);
        gemm_argmin_kernel<<<grid, 256>>>(cb);
        update_kernel<<<BT / 8, 256>>>(cb, out, q);
    }

    ste_kernel<<<(BT * D) / 256, 256>>>(x, out);
    finalize_kernel<<<1, 256>>>(out);
}